// round 4
// baseline (speedup 1.0000x reference)
#include <cuda_runtime.h>

#define V      81616
#define VP     81664   // padded to multiple of 64
#define BATCH  4096
#define DIM    32
#define NCHUNK 16
#define KSPAN  5104    // 16*319; last chunk span = 81616 - 15*5104 = 5056 (mult of 16)

// Scratch (static device globals — allocation-free)
__device__ float g_wT[DIM * VP];               // transposed weights [d][k], tail zero
__device__ float g_part[NCHUNK * BATCH * DIM]; // split-K partial sums
__device__ float g_hs[BATCH * DIM];            // sigmoid(hidden)

// ---------- packed f32x2 helpers ----------
__device__ __forceinline__ void fma2(unsigned long long& acc,
                                     unsigned long long a,
                                     unsigned long long b) {
    asm("fma.rn.f32x2 %0, %1, %2, %0;" : "+l"(acc) : "l"(a), "l"(b));
}
__device__ __forceinline__ float unpack_sum(unsigned long long v) {
    float lo, hi;
    asm("mov.b64 {%0, %1}, %2;" : "=f"(lo), "=f"(hi) : "l"(v));
    return lo + hi;
}
__device__ __forceinline__ float sigmoidf(float z) {
    return __fdividef(1.0f, 1.0f + __expf(-z));
}

// ---------- kernel 1: transpose w [V][32] -> wT [32][VP] (zero-padded) ----------
__global__ void k_transpose(const float* __restrict__ w) {
    __shared__ float s[64][33];
    int k0 = blockIdx.x * 64;
    int tid = threadIdx.x; // 256 threads
#pragma unroll
    for (int i = 0; i < 8; i++) {
        int idx = tid + i * 256;           // 0..2047
        int r = idx >> 5, d = idx & 31;
        int k = k0 + r;
        s[r][d] = (k < V) ? w[(size_t)k * DIM + d] : 0.0f;
    }
    __syncthreads();
#pragma unroll
    for (int i = 0; i < 8; i++) {
        int idx = tid + i * 256;
        int d = idx >> 6, c = idx & 63;
        g_wT[(size_t)d * VP + k0 + c] = s[c][d];
    }
}

// ---------- kernel 2: encoder GEMM, split-K, register-tiled 4x4 ----------
// grid (64 row-tiles, 16 k-chunks), 128 threads.
// warp covers 16 rows x 32 dims; lane = tr*8 + tc (tr: row group, tc: dim group)
__global__ __launch_bounds__(128, 4) void k_encoder(const float* __restrict__ x) {
    int tid  = threadIdx.x;
    int warp = tid >> 5, lane = tid & 31;
    int tr = lane >> 3, tc = lane & 7;
    int row0 = blockIdx.x * 64 + warp * 16 + tr * 4;
    int d0   = tc * 4;
    int chunk = blockIdx.y;
    int kbase = chunk * KSPAN;
    int span  = min(KSPAN, V - kbase);

    const float* px[4];
    const float* pw[4];
#pragma unroll
    for (int i = 0; i < 4; i++) px[i] = x + (size_t)(row0 + i) * V + kbase;
#pragma unroll
    for (int j = 0; j < 4; j++) pw[j] = g_wT + (size_t)(d0 + j) * VP + kbase;

    unsigned long long acc[4][4];
#pragma unroll
    for (int i = 0; i < 4; i++)
#pragma unroll
        for (int j = 0; j < 4; j++) acc[i][j] = 0ull;

#pragma unroll 2
    for (int k = 0; k < span; k += 4) {
        ulonglong2 xv[4], wv[4];
#pragma unroll
        for (int i = 0; i < 4; i++) xv[i] = *(const ulonglong2*)(px[i] + k);
#pragma unroll
        for (int j = 0; j < 4; j++) wv[j] = *(const ulonglong2*)(pw[j] + k);
#pragma unroll
        for (int i = 0; i < 4; i++) {
#pragma unroll
            for (int j = 0; j < 4; j++) {
                fma2(acc[i][j], xv[i].x, wv[j].x);
                fma2(acc[i][j], xv[i].y, wv[j].y);
            }
        }
    }

    // write partials (each (chunk,row,d) written by exactly one thread)
    float* outp = g_part + (size_t)chunk * (BATCH * DIM) + (size_t)row0 * DIM + d0;
#pragma unroll
    for (int i = 0; i < 4; i++) {
        float4 v;
        v.x = unpack_sum(acc[i][0]);
        v.y = unpack_sum(acc[i][1]);
        v.z = unpack_sum(acc[i][2]);
        v.w = unpack_sum(acc[i][3]);
        *(float4*)(outp + (size_t)i * DIM) = v;
    }
}

// ---------- kernel 3: reduce partials + bias + sigmoid ----------
__global__ void k_hidden(const float* __restrict__ b) {
    int i = blockIdx.x * 256 + threadIdx.x; // 131072 total
    float s = 0.0f;
#pragma unroll
    for (int c = 0; c < NCHUNK; c++) s += g_part[(size_t)c * (BATCH * DIM) + i];
    s += b[i & 31];
    g_hs[i] = sigmoidf(s);
}

// ---------- kernel 4: decoder y = sigmoid(hs @ w^T) ----------
// grid (160 col-blocks, 8 row-strips), 256 threads; 2 output columns/thread.
// w row pinned in registers, hs staged in smem and read as broadcasts.
__global__ __launch_bounds__(256, 2) void k_decoder(const float* __restrict__ w,
                                                    float* __restrict__ out) {
    __shared__ float4 hs_s[64][8];
    int tid = threadIdx.x;
    int k1 = blockIdx.x * 512 + tid;
    int k2 = k1 + 256;
    int r_base = blockIdx.y * 512;
    bool v1 = k1 < V, v2 = k2 < V;

    ulonglong2 wA[8], wB[8];
#pragma unroll
    for (int j = 0; j < 8; j++) {
        if (v1) wA[j] = *(const ulonglong2*)(w + (size_t)k1 * DIM + j * 4);
        else { wA[j].x = 0ull; wA[j].y = 0ull; }
        if (v2) wB[j] = *(const ulonglong2*)(w + (size_t)k2 * DIM + j * 4);
        else { wB[j].x = 0ull; wB[j].y = 0ull; }
    }

    for (int r0 = r_base; r0 < r_base + 512; r0 += 64) {
        // stage 64 rows of hs (8 KB)
#pragma unroll
        for (int t = 0; t < 2; t++) {
            int idx = tid + t * 256;               // 0..511
            int rr = idx >> 3, cc = idx & 7;
            hs_s[rr][cc] = *(const float4*)(g_hs + (size_t)(r0 + rr) * DIM + cc * 4);
        }
        __syncthreads();

        for (int r = 0; r < 64; r++) {
            unsigned long long a1e = 0ull, a1o = 0ull, a2e = 0ull, a2o = 0ull;
#pragma unroll
            for (int j = 0; j < 8; j++) {
                ulonglong2 h2 = *(const ulonglong2*)&hs_s[r][j];
                fma2(a1e, h2.x, wA[j].x);
                fma2(a1o, h2.y, wA[j].y);
                fma2(a2e, h2.x, wB[j].x);
                fma2(a2o, h2.y, wB[j].y);
            }
            float z1 = unpack_sum(a1e) + unpack_sum(a1o);
            float z2 = unpack_sum(a2e) + unpack_sum(a2o);
            float y1 = sigmoidf(z1);
            float y2 = sigmoidf(z2);
            size_t ro = (size_t)(r0 + r) * V;
            if (v1) out[ro + k1] = y1;
            if (v2) out[ro + k2] = y2;
        }
        __syncthreads();
    }
}

extern "C" void kernel_launch(void* const* d_in, const int* in_sizes, int n_in,
                              void* d_out, int out_size) {
    const float* x = (const float*)d_in[0];
    const float* w = (const float*)d_in[1];
    const float* b = (const float*)d_in[2];
    float* out = (float*)d_out;

    k_transpose<<<VP / 64, 256>>>(w);
    k_encoder<<<dim3(64, 16), 128>>>(x);
    k_hidden<<<(BATCH * DIM) / 256, 256>>>(b);
    k_decoder<<<dim3(160, 8), 256>>>(w, out);
}

// round 5
// speedup vs baseline: 1.9662x; 1.9662x over previous
#include <cuda_runtime.h>

#define V      81616
#define VP     81920           // padded k extent for wT
#define BATCH  4096
#define DIM    32
#define KC     32              // k-chunk per smem stage (encoder)
#define SPLITS 18
#define SPAN   4544            // 142 * 32 ; 18*4544 = 81792 >= V

// Scratch (static device globals — allocation-free)
__device__ float g_wT[DIM * VP];                 // transposed weights [d][k], zero tail
__device__ float g_part[SPLITS * BATCH * DIM];   // split-K partials
__device__ float g_hs[BATCH * DIM];              // sigmoid(hidden)

// ---------- packed f32x2 helpers ----------
__device__ __forceinline__ void fma2(unsigned long long& acc,
                                     unsigned long long a,
                                     unsigned long long b) {
    asm("fma.rn.f32x2 %0, %1, %2, %0;" : "+l"(acc) : "l"(a), "l"(b));
}
__device__ __forceinline__ unsigned long long add2(unsigned long long a,
                                                   unsigned long long b) {
    unsigned long long c;
    asm("add.rn.f32x2 %0, %1, %2;" : "=l"(c) : "l"(a), "l"(b));
    return c;
}
__device__ __forceinline__ float unpack_sum(unsigned long long v) {
    float lo, hi;
    asm("mov.b64 {%0, %1}, %2;" : "=f"(lo), "=f"(hi) : "l"(v));
    return lo + hi;
}
__device__ __forceinline__ float sigmoidf(float z) {
    return __fdividef(1.0f, 1.0f + __expf(-z));
}

// ---------- kernel 1: transpose w [V][32] -> wT [32][VP] (zero-padded) ----------
__global__ void k_transpose(const float* __restrict__ w) {
    __shared__ float s[64][33];
    int k0 = blockIdx.x * 64;
    int tid = threadIdx.x; // 256 threads
#pragma unroll
    for (int i = 0; i < 8; i++) {
        int idx = tid + i * 256;           // 0..2047
        int r = idx >> 5, d = idx & 31;
        int k = k0 + r;
        s[r][d] = (k < V) ? w[(size_t)k * DIM + d] : 0.0f;
    }
    __syncthreads();
#pragma unroll
    for (int i = 0; i < 8; i++) {
        int idx = tid + i * 256;
        int d = idx >> 6, c = idx & 63;
        g_wT[(size_t)d * VP + k0 + c] = s[c][d];
    }
}

// ---------- kernel 2: encoder GEMM, smem-staged, split-K ----------
// Block: 256 threads, tile 256 rows x 32 dims. Thread: 8 rows x 4 dims.
// Warp covers 32 rows: lane = lg*8? no: dg = lane&7 (dim group), lg = lane>>3.
// Thread rows: warp*32 + lg + 4*i  (adjacent lanes -> adjacent rows: conflict-free
// with 36-float row padding). w staged as k-pairs with phi(d) permutation so the
// 8 dim-group lanes read 64 contiguous bytes (conflict-free LDS.64 + 4-way bcast).
__global__ __launch_bounds__(256, 2) void k_encoder(const float* __restrict__ x) {
    __shared__ __align__(16) float  xs[256][36];
    __shared__ __align__(16) float2 ws2[KC / 2][32];

    int tid  = threadIdx.x;
    int warp = tid >> 5;
    int lane = tid & 31;
    int dg   = lane & 7;          // dim group: dims 4*dg .. 4*dg+3
    int lg   = lane >> 3;         // row sub-group 0..3
    int lrow0 = warp * 32 + lg;   // local row base; rows lrow0 + 4*i
    int row0  = blockIdx.x * 256; // global row tile base

    int split = blockIdx.y;
    int k0   = split * SPAN;
    int kend = min(V, k0 + SPAN);

    unsigned long long acc[8][4];
#pragma unroll
    for (int i = 0; i < 8; i++)
#pragma unroll
        for (int j = 0; j < 4; j++) acc[i][j] = 0ull;

    int sd = tid >> 3, skq = tid & 7;   // for ws staging: 32 d x 8 kq
    int ph = ((sd & 3) << 3) + (sd >> 2);

#pragma unroll 1
    for (int kb = k0; kb < kend; kb += KC) {
        // ---- stage x tile: 256 rows x 32 k (coalesced; guarded tail) ----
#pragma unroll
        for (int i = 0; i < 8; i++) {
            int idx = tid + i * 256;       // 0..2047
            int r  = idx >> 3;
            int kq = idx & 7;
            int gk = kb + (kq << 2);
            const float* src = x + (size_t)(row0 + r) * V;
            float4 v;
            if (gk + 3 < V) {
                v = *(const float4*)(src + gk);
            } else {
                v.x = (gk     < V) ? src[gk]     : 0.0f;
                v.y = (gk + 1 < V) ? src[gk + 1] : 0.0f;
                v.z = (gk + 2 < V) ? src[gk + 2] : 0.0f;
                v.w = (gk + 3 < V) ? src[gk + 3] : 0.0f;
            }
            *(float4*)&xs[r][kq << 2] = v;
        }
        // ---- stage w pairs: ws2[k2][phi(d)] = (w[d][2k2], w[d][2k2+1]) ----
        {
            float4 wv4 = *(const float4*)(g_wT + (size_t)sd * VP + kb + (skq << 2));
            ws2[(skq << 1)    ][ph] = make_float2(wv4.x, wv4.y);
            ws2[(skq << 1) + 1][ph] = make_float2(wv4.z, wv4.w);
        }
        __syncthreads();

        // ---- compute ----
#pragma unroll
        for (int kk = 0; kk < KC; kk += 4) {
            int k2 = kk >> 1;
            unsigned long long wva[4], wvb[4];
#pragma unroll
            for (int j = 0; j < 4; j++) {
                wva[j] = *(const unsigned long long*)&ws2[k2    ][(j << 3) + dg];
                wvb[j] = *(const unsigned long long*)&ws2[k2 + 1][(j << 3) + dg];
            }
#pragma unroll
            for (int i = 0; i < 8; i++) {
                ulonglong2 xv = *(const ulonglong2*)&xs[lrow0 + (i << 2)][kk];
#pragma unroll
                for (int j = 0; j < 4; j++) {
                    fma2(acc[i][j], xv.x, wva[j]);
                    fma2(acc[i][j], xv.y, wvb[j]);
                }
            }
        }
        __syncthreads();
    }

    // ---- write partials ----
    int d0 = dg << 2;
#pragma unroll
    for (int i = 0; i < 8; i++) {
        int grow = row0 + lrow0 + (i << 2);
        float4 v;
        v.x = unpack_sum(acc[i][0]);
        v.y = unpack_sum(acc[i][1]);
        v.z = unpack_sum(acc[i][2]);
        v.w = unpack_sum(acc[i][3]);
        *(float4*)(g_part + (size_t)split * (BATCH * DIM) + (size_t)grow * DIM + d0) = v;
    }
}

// ---------- kernel 3: reduce partials + bias + sigmoid ----------
__global__ void k_hidden(const float* __restrict__ b) {
    int i = blockIdx.x * 256 + threadIdx.x; // 131072 total
    float s = 0.0f;
#pragma unroll
    for (int c = 0; c < SPLITS; c++) s += g_part[(size_t)c * (BATCH * DIM) + i];
    s += b[i & 31];
    g_hs[i] = sigmoidf(s);
}

// ---------- kernel 4: decoder y = sigmoid(hs @ w^T) ----------
// grid (160 col-blocks, 8 row-strips), 256 threads; 2 ADJACENT output columns
// per thread -> STG.64, coalesced. w rows pinned in registers; hs staged 128
// rows at a time in smem and consumed as broadcast LDS.128.
#define DSTAGE 128
__global__ __launch_bounds__(256, 2) void k_decoder(const float* __restrict__ w,
                                                    float* __restrict__ out) {
    __shared__ __align__(16) float4 hs_s[DSTAGE][8];
    int tid = threadIdx.x;
    int k1 = blockIdx.x * 512 + tid * 2;   // cols k1, k1+1 (V even -> pair valid together)
    bool v = (k1 < V);
    int r_base = blockIdx.y * 512;

    ulonglong2 wA[8], wB[8];
#pragma unroll
    for (int j = 0; j < 8; j++) {
        if (v) {
            wA[j] = *(const ulonglong2*)(w + (size_t)k1 * DIM + j * 4);
            wB[j] = *(const ulonglong2*)(w + (size_t)(k1 + 1) * DIM + j * 4);
        } else {
            wA[j].x = wA[j].y = 0ull;
            wB[j].x = wB[j].y = 0ull;
        }
    }

    for (int r0 = r_base; r0 < r_base + 512; r0 += DSTAGE) {
        // stage DSTAGE rows of hs (16 KB)
#pragma unroll
        for (int t = 0; t < 4; t++) {
            int idx = tid + t * 256;             // 0..1023
            int rr = idx >> 3, cc = idx & 7;
            hs_s[rr][cc] = *(const float4*)(g_hs + (size_t)(r0 + rr) * DIM + cc * 4);
        }
        __syncthreads();

        for (int r = 0; r < DSTAGE; r++) {
            unsigned long long a1e = 0ull, a1o = 0ull, a2e = 0ull, a2o = 0ull;
#pragma unroll
            for (int j = 0; j < 8; j++) {
                ulonglong2 h2 = *(const ulonglong2*)&hs_s[r][j];
                fma2(a1e, h2.x, wA[j].x);
                fma2(a1o, h2.y, wA[j].y);
                fma2(a2e, h2.x, wB[j].x);
                fma2(a2o, h2.y, wB[j].y);
            }
            float z1 = unpack_sum(add2(a1e, a1o));
            float z2 = unpack_sum(add2(a2e, a2o));
            float2 y;
            y.x = sigmoidf(z1);
            y.y = sigmoidf(z2);
            if (v) *(float2*)(out + (size_t)(r0 + r) * V + k1) = y;
        }
        __syncthreads();
    }
}

extern "C" void kernel_launch(void* const* d_in, const int* in_sizes, int n_in,
                              void* d_out, int out_size) {
    const float* x = (const float*)d_in[0];
    const float* w = (const float*)d_in[1];
    const float* b = (const float*)d_in[2];
    float* out = (float*)d_out;

    k_transpose<<<VP / 64, 256>>>(w);
    k_encoder<<<dim3(BATCH / 256, SPLITS), 256>>>(x);
    k_hidden<<<(BATCH * DIM) / 256, 256>>>(b);
    k_decoder<<<dim3(160, 8), 256>>>(w, out);
}

// round 6
// speedup vs baseline: 2.6602x; 1.3530x over previous
#include <cuda_runtime.h>

#define V      81616
#define VP     81920           // padded k extent for wT
#define BATCH  4096
#define DIM    32
#define KC     16              // k-chunk per smem stage (encoder)
#define SPLITS 18
#define SPAN   4544            // multiple of 16; 18*4544 >= V; last span 4368 (mult of 16)

// Scratch (static device globals — allocation-free)
__device__ float g_wT[DIM * VP];                 // transposed weights [d][k], zero tail
__device__ float g_part[SPLITS * BATCH * DIM];   // split-K partials
__device__ float g_hs[BATCH * DIM];              // sigmoid(hidden)

// ---------- packed f32x2 helpers ----------
__device__ __forceinline__ void fma2(unsigned long long& acc,
                                     unsigned long long a,
                                     unsigned long long b) {
    asm("fma.rn.f32x2 %0, %1, %2, %0;" : "+l"(acc) : "l"(a), "l"(b));
}
__device__ __forceinline__ unsigned long long add2(unsigned long long a,
                                                   unsigned long long b) {
    unsigned long long c;
    asm("add.rn.f32x2 %0, %1, %2;" : "=l"(c) : "l"(a), "l"(b));
    return c;
}
__device__ __forceinline__ float unpack_sum(unsigned long long v) {
    float lo, hi;
    asm("mov.b64 {%0, %1}, %2;" : "=f"(lo), "=f"(hi) : "l"(v));
    return lo + hi;
}
__device__ __forceinline__ float sigmoidf(float z) {
    return __fdividef(1.0f, 1.0f + __expf(-z));
}

// ---------- cp.async helpers ----------
__device__ __forceinline__ void cp16(void* dst_smem, const void* src) {
    unsigned d = (unsigned)__cvta_generic_to_shared(dst_smem);
    asm volatile("cp.async.cg.shared.global [%0], [%1], 16;" :: "r"(d), "l"(src));
}
__device__ __forceinline__ void cp8(void* dst_smem, const void* src) {
    unsigned d = (unsigned)__cvta_generic_to_shared(dst_smem);
    asm volatile("cp.async.ca.shared.global [%0], [%1], 8;" :: "r"(d), "l"(src));
}
__device__ __forceinline__ void cp_commit() {
    asm volatile("cp.async.commit_group;");
}
template <int N>
__device__ __forceinline__ void cp_wait() {
    asm volatile("cp.async.wait_group %0;" :: "n"(N));
}

// ---------- kernel 1: transpose w [V][32] -> wT [32][VP] (zero-padded) ----------
__global__ void k_transpose(const float* __restrict__ w) {
    __shared__ float s[64][33];
    int k0 = blockIdx.x * 64;
    int tid = threadIdx.x; // 256 threads
#pragma unroll
    for (int i = 0; i < 8; i++) {
        int idx = tid + i * 256;           // 0..2047
        int r = idx >> 5, d = idx & 31;
        int k = k0 + r;
        s[r][d] = (k < V) ? w[(size_t)k * DIM + d] : 0.0f;
    }
    __syncthreads();
#pragma unroll
    for (int i = 0; i < 8; i++) {
        int idx = tid + i * 256;
        int d = idx >> 6, c = idx & 63;
        g_wT[(size_t)d * VP + k0 + c] = s[c][d];
    }
}

// ---------- kernel 2: encoder GEMM, cp.async double-buffered, split-K ----------
// Block: 256 threads, tile 256 rows x 32 dims. Thread: 8 rows x 4 dims.
// xs rows padded to 20 floats (bank shift 4/row, adjacent-lane rows -> 1 phase).
// ws staged as k-pairs with phi(d) permutation -> conflict-free broadcast LDS.64.
__global__ __launch_bounds__(256, 2) void k_encoder(const float* __restrict__ x) {
    __shared__ __align__(16) float  xs[2][256][20];
    __shared__ __align__(16) float2 ws2[2][KC / 2][32];

    int tid  = threadIdx.x;
    int warp = tid >> 5;
    int lane = tid & 31;
    int dg   = lane & 7;          // dim group: dims 4*dg .. 4*dg+3
    int lg   = lane >> 3;         // row sub-group 0..3
    int lrow0 = warp * 32 + lg;   // local rows: lrow0 + 4*i
    int row0  = blockIdx.x * 256;

    int split = blockIdx.y;
    int k0   = split * SPAN;
    int kend = min(V, k0 + SPAN);
    int nstg = (kend - k0) / KC;  // exact: spans are multiples of 16

    // staging indices (all in-bounds; V and spans are multiples of 16)
    int sr  = tid >> 2;           // x stage: row 0..63 (+64*i)
    int skq = tid & 3;            // x stage: 16B chunk 0..3
    int sd  = tid >> 3;           // w stage: d 0..31
    int sk2 = tid & 7;            // w stage: k-pair 0..7
    int ph  = ((sd & 3) << 3) + (sd >> 2);
    const float* xbase = x + (size_t)row0 * V + (size_t)(skq << 2);
    const float* wbase = g_wT + (size_t)sd * VP + (sk2 << 1);

    unsigned long long acc[8][4];
#pragma unroll
    for (int i = 0; i < 8; i++)
#pragma unroll
        for (int j = 0; j < 4; j++) acc[i][j] = 0ull;

    // ---- prologue: stage 0 into buffer 0 ----
    {
        const float* xsrc = xbase + k0;
#pragma unroll
        for (int i = 0; i < 4; i++)
            cp16(&xs[0][sr + i * 64][skq << 2], xsrc + (size_t)(sr + i * 64) * V);
        cp8(&ws2[0][sk2][ph], wbase + k0);
    }
    cp_commit();

#pragma unroll 1
    for (int s = 0; s < nstg; s++) {
        int buf = s & 1;
        // prefetch stage s+1 into the other buffer (its previous contents were
        // consumed at iteration s-1; barrier at end of that iter protects it)
        if (s + 1 < nstg) {
            int kb = k0 + (s + 1) * KC;
            const float* xsrc = xbase + kb;
            int nb = buf ^ 1;
#pragma unroll
            for (int i = 0; i < 4; i++)
                cp16(&xs[nb][sr + i * 64][skq << 2], xsrc + (size_t)(sr + i * 64) * V);
            cp8(&ws2[nb][sk2][ph], wbase + kb);
        }
        cp_commit();
        cp_wait<1>();          // stage s complete (s+1 may be in flight)
        __syncthreads();

        // ---- compute on buffer s&1 ----
#pragma unroll
        for (int kk = 0; kk < KC; kk += 4) {
            int k2 = kk >> 1;
            unsigned long long wva[4], wvb[4];
#pragma unroll
            for (int j = 0; j < 4; j++) {
                wva[j] = *(const unsigned long long*)&ws2[buf][k2    ][(j << 3) + dg];
                wvb[j] = *(const unsigned long long*)&ws2[buf][k2 + 1][(j << 3) + dg];
            }
#pragma unroll
            for (int i = 0; i < 8; i++) {
                ulonglong2 xv = *(const ulonglong2*)&xs[buf][lrow0 + (i << 2)][kk];
#pragma unroll
                for (int j = 0; j < 4; j++) {
                    fma2(acc[i][j], xv.x, wva[j]);
                    fma2(acc[i][j], xv.y, wvb[j]);
                }
            }
        }
        __syncthreads();       // buffer free for prefetch s+2
    }

    // ---- write partials ----
    int d0 = dg << 2;
#pragma unroll
    for (int i = 0; i < 8; i++) {
        int grow = row0 + lrow0 + (i << 2);
        float4 v;
        v.x = unpack_sum(acc[i][0]);
        v.y = unpack_sum(acc[i][1]);
        v.z = unpack_sum(acc[i][2]);
        v.w = unpack_sum(acc[i][3]);
        *(float4*)(g_part + (size_t)split * (BATCH * DIM) + (size_t)grow * DIM + d0) = v;
    }
}

// ---------- kernel 3: reduce partials + bias + sigmoid ----------
__global__ void k_hidden(const float* __restrict__ b) {
    int i = blockIdx.x * 256 + threadIdx.x; // 131072 total
    float s = 0.0f;
#pragma unroll
    for (int c = 0; c < SPLITS; c++) s += g_part[(size_t)c * (BATCH * DIM) + i];
    s += b[i & 31];
    g_hs[i] = sigmoidf(s);
}

// ---------- kernel 4: decoder y = sigmoid(hs @ w^T) ----------
// grid (160 col-blocks, 8 row-strips), 256 threads; 2 ADJACENT output columns
// per thread -> STG.64. w rows pinned in registers; hs staged 128 rows in smem,
// consumed as broadcast LDS.128. Inner loop unrolled 2 rows for ILP.
#define DSTAGE 128
__global__ __launch_bounds__(256, 2) void k_decoder(const float* __restrict__ w,
                                                    float* __restrict__ out) {
    __shared__ __align__(16) float4 hs_s[DSTAGE][8];
    int tid = threadIdx.x;
    int k1 = blockIdx.x * 512 + tid * 2;   // cols k1, k1+1 (V even)
    bool v = (k1 < V);
    int r_base = blockIdx.y * 512;

    ulonglong2 wA[8], wB[8];
#pragma unroll
    for (int j = 0; j < 8; j++) {
        if (v) {
            wA[j] = *(const ulonglong2*)(w + (size_t)k1 * DIM + j * 4);
            wB[j] = *(const ulonglong2*)(w + (size_t)(k1 + 1) * DIM + j * 4);
        } else {
            wA[j].x = wA[j].y = 0ull;
            wB[j].x = wB[j].y = 0ull;
        }
    }

    for (int r0 = r_base; r0 < r_base + 512; r0 += DSTAGE) {
        // stage DSTAGE rows of hs (16 KB)
#pragma unroll
        for (int t = 0; t < 4; t++) {
            int idx = tid + t * 256;             // 0..1023
            int rr = idx >> 3, cc = idx & 7;
            hs_s[rr][cc] = *(const float4*)(g_hs + (size_t)(r0 + rr) * DIM + cc * 4);
        }
        __syncthreads();

#pragma unroll 1
        for (int r = 0; r < DSTAGE; r += 2) {
            unsigned long long p1e = 0ull, p1o = 0ull, p2e = 0ull, p2o = 0ull;
            unsigned long long q1e = 0ull, q1o = 0ull, q2e = 0ull, q2o = 0ull;
#pragma unroll
            for (int j = 0; j < 8; j++) {
                ulonglong2 ha = *(const ulonglong2*)&hs_s[r][j];
                ulonglong2 hb = *(const ulonglong2*)&hs_s[r + 1][j];
                fma2(p1e, ha.x, wA[j].x);
                fma2(p1o, ha.y, wA[j].y);
                fma2(p2e, ha.x, wB[j].x);
                fma2(p2o, ha.y, wB[j].y);
                fma2(q1e, hb.x, wA[j].x);
                fma2(q1o, hb.y, wA[j].y);
                fma2(q2e, hb.x, wB[j].x);
                fma2(q2o, hb.y, wB[j].y);
            }
            float2 ya, yb;
            ya.x = sigmoidf(unpack_sum(add2(p1e, p1o)));
            ya.y = sigmoidf(unpack_sum(add2(p2e, p2o)));
            yb.x = sigmoidf(unpack_sum(add2(q1e, q1o)));
            yb.y = sigmoidf(unpack_sum(add2(q2e, q2o)));
            if (v) {
                *(float2*)(out + (size_t)(r0 + r) * V + k1) = ya;
                *(float2*)(out + (size_t)(r0 + r + 1) * V + k1) = yb;
            }
        }
        __syncthreads();
    }
}

extern "C" void kernel_launch(void* const* d_in, const int* in_sizes, int n_in,
                              void* d_out, int out_size) {
    const float* x = (const float*)d_in[0];
    const float* w = (const float*)d_in[1];
    const float* b = (const float*)d_in[2];
    float* out = (float*)d_out;

    k_transpose<<<VP / 64, 256>>>(w);
    k_encoder<<<dim3(BATCH / 256, SPLITS), 256>>>(x);
    k_hidden<<<(BATCH * DIM) / 256, 256>>>(b);
    k_decoder<<<dim3(160, 8), 256>>>(w, out);
}

// round 8
// speedup vs baseline: 5.9036x; 2.2192x over previous
#include <cuda_runtime.h>
#include <cstdint>

#define V      81616
#define BATCH  4096
#define DIM    32
#define SPLITS 18
#define SPAN   4544            // 142*32; last split span 4368 (136*32 + 16)
#define KC     32
#define NW     192             // decoder column span per CTA

// Scratch (static device globals — allocation-free)
__device__ float g_part[SPLITS * BATCH * DIM];   // split-K partials
__device__ float g_hs[BATCH * DIM];              // sigmoid(hidden)

// ---------- helpers ----------
__device__ __forceinline__ void cp16(void* dst_smem, const void* src) {
    unsigned d = (unsigned)__cvta_generic_to_shared(dst_smem);
    asm volatile("cp.async.cg.shared.global [%0], [%1], 16;" :: "r"(d), "l"(src));
}
__device__ __forceinline__ void cp_commit() {
    asm volatile("cp.async.commit_group;");
}
template <int N>
__device__ __forceinline__ void cp_wait() {
    asm volatile("cp.async.wait_group %0;" :: "n"(N));
}
__device__ __forceinline__ uint32_t tf32(float f) {
    uint32_t u;
    asm("cvt.rna.tf32.f32 %0, %1;" : "=r"(u) : "f"(f));
    return u;
}
__device__ __forceinline__ void mma8(float& d0, float& d1, float& d2, float& d3,
                                     uint32_t a0, uint32_t a1, uint32_t a2, uint32_t a3,
                                     uint32_t b0, uint32_t b1) {
    asm("mma.sync.aligned.m16n8k8.row.col.f32.tf32.tf32.f32 "
        "{%0,%1,%2,%3}, {%4,%5,%6,%7}, {%8,%9}, {%0,%1,%2,%3};"
        : "+f"(d0), "+f"(d1), "+f"(d2), "+f"(d3)
        : "r"(a0), "r"(a1), "r"(a2), "r"(a3), "r"(b0), "r"(b1));
}
__device__ __forceinline__ float sig_tanh(float z) {
    float t;
    asm("tanh.approx.f32 %0, %1;" : "=f"(t) : "f"(0.5f * z));
    return fmaf(0.5f, t, 0.5f);
}
__device__ __forceinline__ float sig_exact(float z) {
    return __fdividef(1.0f, 1.0f + __expf(-z));
}

// ---------- kernel 1: encoder  part[split] += x[128 x Kspan] * w[Kspan x 32] ----------
// 256 threads = 8 warps x m16. A (x) frags from xs (pad 36), B (w, natural
// [k][32] layout) frags from ws (pad 40). cp.async double-buffered, KC=32.
__global__ __launch_bounds__(256, 4) void k_encoder(const float* __restrict__ x,
                                                    const float* __restrict__ w) {
    __shared__ __align__(16) float xs[2][128][36];   // 36864 B
    __shared__ __align__(16) float ws[2][32][40];    // 10240 B

    int tid  = threadIdx.x;
    int warp = tid >> 5, lane = tid & 31;
    int l4 = lane >> 2, lm4 = lane & 3;
    int wr0 = warp * 16;
    int row0  = blockIdx.x * 128;
    int split = blockIdx.y;
    int k0    = split * SPAN;
    int kspan = min(SPAN, V - k0);
    int nstg  = (kspan + KC - 1) / KC;

    const size_t XMAX = (size_t)BATCH * V - 4;

    float acc[4][4];
#pragma unroll
    for (int j = 0; j < 4; j++)
#pragma unroll
        for (int c = 0; c < 4; c++) acc[j][c] = 0.0f;

    int wkl = tid >> 3, wc = tid & 7;   // w staging: k-row 0..31, chunk 0..7

    auto stage = [&](int s, int slot) {
        int kb = k0 + s * KC;
#pragma unroll
        for (int i = 0; i < 4; i++) {
            int idx = tid + 256 * i;
            int r = idx >> 3, c = idx & 7;
            size_t off = (size_t)(row0 + r) * V + kb + (c << 2);
            if (off > XMAX) off = XMAX;   // finite garbage; matching w rows are zeroed
            cp16(&xs[slot][r][c << 2], x + off);
        }
        if (kb + wkl < V) {
            cp16(&ws[slot][wkl][wc << 2], w + (size_t)(kb + wkl) * DIM + (wc << 2));
        } else {
            *(float4*)&ws[slot][wkl][wc << 2] = make_float4(0.f, 0.f, 0.f, 0.f);
        }
    };

    stage(0, 0);
    cp_commit();

#pragma unroll 1
    for (int s = 0; s < nstg; s++) {
        int slot = s & 1;
        if (s + 1 < nstg) {
            stage(s + 1, slot ^ 1);
            cp_commit();
            cp_wait<1>();
        } else {
            cp_commit();
            cp_wait<0>();
        }
        __syncthreads();

        const float* xsb = &xs[slot][wr0 + l4][lm4];
        const float* wsb = &ws[slot][lm4][l4];
#pragma unroll
        for (int kk = 0; kk < 4; kk++) {
            uint32_t a0 = tf32(xsb[kk * 8]);
            uint32_t a1 = tf32(xsb[288 + kk * 8]);
            uint32_t a2 = tf32(xsb[kk * 8 + 4]);
            uint32_t a3 = tf32(xsb[288 + kk * 8 + 4]);
#pragma unroll
            for (int j = 0; j < 4; j++) {
                uint32_t b0 = tf32(wsb[kk * 320 + j * 8]);
                uint32_t b1 = tf32(wsb[kk * 320 + 160 + j * 8]);
                mma8(acc[j][0], acc[j][1], acc[j][2], acc[j][3],
                     a0, a1, a2, a3, b0, b1);
            }
        }
        __syncthreads();
    }

    // epilogue: D frag c0,c1 at (row l4, col 2*lm4 .. +1); c2,c3 at row+8
    float* p = g_part + (size_t)split * (BATCH * DIM)
             + (size_t)(row0 + wr0 + l4) * DIM + lm4 * 2;
#pragma unroll
    for (int j = 0; j < 4; j++) {
        *(float2*)(p + j * 8)            = make_float2(acc[j][0], acc[j][1]);
        *(float2*)(p + 8 * DIM + j * 8)  = make_float2(acc[j][2], acc[j][3]);
    }
}

// ---------- kernel 2: reduce partials + bias + sigmoid (exact) ----------
__global__ void k_hidden(const float* __restrict__ b) {
    int i = blockIdx.x * 256 + threadIdx.x; // 131072 total
    float s = 0.0f;
#pragma unroll
    for (int c = 0; c < SPLITS; c++) s += g_part[(size_t)c * (BATCH * DIM) + i];
    s += b[i & 31];
    g_hs[i] = sig_exact(s);
}

// ---------- kernel 3: decoder y = sigmoid(hs @ w^T) via mma tf32 ----------
// CTA: 128 rows x NW cols; warp = m16 strip, A (hs) frags in registers for the
// whole column sweep. B frags straight from natural w[v][32] (pad 36).
__global__ __launch_bounds__(256, 3) void k_decoder(const float* __restrict__ w,
                                                    float* __restrict__ out) {
    __shared__ __align__(16) float hs_s[128][36];   // 18432 B
    __shared__ __align__(16) float wv_s[NW][36];    // 27648 B

    int tid  = threadIdx.x;
    int warp = tid >> 5, lane = tid & 31;
    int l4 = lane >> 2, lm4 = lane & 3;
    int wr0 = warp * 16;
    int m0 = blockIdx.y * 128;
    int n0 = blockIdx.x * NW;

    // stage hs: 128 rows x 128 B
#pragma unroll
    for (int i = 0; i < 4; i++) {
        int idx = tid + 256 * i;
        int r = idx >> 3, c = idx & 7;
        cp16(&hs_s[r][c << 2], g_hs + (size_t)(m0 + r) * DIM + (c << 2));
    }
    // stage w: NW rows x 128 B (clamped; cols >= V never stored)
#pragma unroll
    for (int i = 0; i < 6; i++) {
        int idx = tid + 256 * i;
        int vrow = idx >> 3, c = idx & 7;
        int vs = n0 + vrow;
        if (vs > V - 1) vs = V - 1;
        cp16(&wv_s[vrow][c << 2], w + (size_t)vs * DIM + (c << 2));
    }
    cp_commit();
    cp_wait<0>();
    __syncthreads();

    // A frags (m16 x k32) once per warp
    uint32_t ua[4][4];
    const float* hb = &hs_s[wr0 + l4][lm4];
#pragma unroll
    for (int kk = 0; kk < 4; kk++) {
        ua[kk][0] = tf32(hb[kk * 8]);
        ua[kk][1] = tf32(hb[288 + kk * 8]);
        ua[kk][2] = tf32(hb[kk * 8 + 4]);
        ua[kk][3] = tf32(hb[288 + kk * 8 + 4]);
    }

    int jmax = min(NW / 8, (V - n0) >> 3);   // V is a multiple of 8
    const float* wb = &wv_s[l4][lm4];
    float* o0 = out + (size_t)(m0 + wr0 + l4) * V + n0 + lm4 * 2;
    float* o1 = o0 + (size_t)8 * V;

#pragma unroll 2
    for (int j = 0; j < jmax; j++) {
        float d0 = 0.f, d1 = 0.f, d2 = 0.f, d3 = 0.f;
#pragma unroll
        for (int kk = 0; kk < 4; kk++) {
            uint32_t b0 = tf32(wb[j * 288 + kk * 8]);
            uint32_t b1 = tf32(wb[j * 288 + kk * 8 + 4]);
            mma8(d0, d1, d2, d3,
                 ua[kk][0], ua[kk][1], ua[kk][2], ua[kk][3], b0, b1);
        }
        *(float2*)(o0 + j * 8) = make_float2(sig_tanh(d0), sig_tanh(d1));
        *(float2*)(o1 + j * 8) = make_float2(sig_tanh(d2), sig_tanh(d3));
    }
}

extern "C" void kernel_launch(void* const* d_in, const int* in_sizes, int n_in,
                              void* d_out, int out_size) {
    const float* x = (const float*)d_in[0];
    const float* w = (const float*)d_in[1];
    const float* b = (const float*)d_in[2];
    float* out = (float*)d_out;

    k_encoder<<<dim3(BATCH / 128, SPLITS), 256>>>(x, w);
    k_hidden<<<(BATCH * DIM) / 256, 256>>>(b);
    k_decoder<<<dim3((V + NW - 1) / NW, BATCH / 128), 256>>>(w, out);
}

// round 9
// speedup vs baseline: 5.9383x; 1.0059x over previous
#include <cuda_runtime.h>
#include <cstdint>

#define V      81616
#define BATCH  4096
#define DIM    32
#define SPLITS 18
#define SPAN   4544            // 142*32; last split span 4368
#define KC     32
#define NW     192             // decoder column span per CTA

// Scratch (static device globals — allocation-free)
__device__ float g_part[SPLITS * BATCH * DIM];   // split-K partials
__device__ float g_hs[BATCH * DIM];              // sigmoid(hidden)
__device__ float g_wc[V * DIM];                  // w pre-rounded to tf32 (rna)

// ---------- helpers ----------
__device__ __forceinline__ void cp16(void* dst_smem, const void* src) {
    unsigned d = (unsigned)__cvta_generic_to_shared(dst_smem);
    asm volatile("cp.async.cg.shared.global [%0], [%1], 16;" :: "r"(d), "l"(src));
}
__device__ __forceinline__ void cp_commit() {
    asm volatile("cp.async.commit_group;");
}
template <int N>
__device__ __forceinline__ void cp_wait() {
    asm volatile("cp.async.wait_group %0;" :: "n"(N));
}
__device__ __forceinline__ uint32_t tf32(float f) {
    uint32_t u;
    asm("cvt.rna.tf32.f32 %0, %1;" : "=r"(u) : "f"(f));
    return u;
}
__device__ __forceinline__ void mma8(float& d0, float& d1, float& d2, float& d3,
                                     uint32_t a0, uint32_t a1, uint32_t a2, uint32_t a3,
                                     uint32_t b0, uint32_t b1) {
    asm("mma.sync.aligned.m16n8k8.row.col.f32.tf32.tf32.f32 "
        "{%0,%1,%2,%3}, {%4,%5,%6,%7}, {%8,%9}, {%0,%1,%2,%3};"
        : "+f"(d0), "+f"(d1), "+f"(d2), "+f"(d3)
        : "r"(a0), "r"(a1), "r"(a2), "r"(a3), "r"(b0), "r"(b1));
}
__device__ __forceinline__ float sig_tanh(float z) {
    float t;
    asm("tanh.approx.f32 %0, %1;" : "=f"(t) : "f"(0.5f * z));
    return fmaf(0.5f, t, 0.5f);
}
__device__ __forceinline__ float sig_exact(float z) {
    return __fdividef(1.0f, 1.0f + __expf(-z));
}

// ---------- kernel 0: pre-round w to tf32 (rna) ----------
__global__ void k_wconv(const float* __restrict__ w) {
    int i = blockIdx.x * 1024 + threadIdx.x * 4;
    if (i + 3 < V * DIM) {
        float4 v = *(const float4*)(w + i);
        uint4 o;
        o.x = tf32(v.x); o.y = tf32(v.y); o.z = tf32(v.z); o.w = tf32(v.w);
        *(uint4*)(g_wc + i) = o;
    } else if (i < V * DIM) {
        for (int t = i; t < V * DIM; t++)
            *(uint32_t*)(g_wc + t) = tf32(w[t]);
    }
}

// ---------- kernel 1: encoder  part[split] += x[128 x Kspan] * w[Kspan x 32] ----------
// 256 threads = 8 warps x m16. No in-loop cvt: x raw bits (tf32 truncation),
// w pre-rounded in g_wc. cp.async double-buffered, KC=32.
__global__ __launch_bounds__(256, 4) void k_encoder(const float* __restrict__ x) {
    __shared__ __align__(16) float xs[2][128][36];   // 36864 B
    __shared__ __align__(16) float ws[2][32][40];    // 10240 B

    int tid  = threadIdx.x;
    int warp = tid >> 5, lane = tid & 31;
    int l4 = lane >> 2, lm4 = lane & 3;
    int wr0 = warp * 16;
    int row0  = blockIdx.x * 128;
    int split = blockIdx.y;
    int k0    = split * SPAN;
    int kspan = min(SPAN, V - k0);
    int nstg  = (kspan + KC - 1) / KC;

    const size_t XMAX = (size_t)BATCH * V - 4;

    float acc[4][4];
#pragma unroll
    for (int j = 0; j < 4; j++)
#pragma unroll
        for (int c = 0; c < 4; c++) acc[j][c] = 0.0f;

    int wkl = tid >> 3, wc = tid & 7;   // w staging: k-row 0..31, chunk 0..7

    auto stage = [&](int s, int slot) {
        int kb = k0 + s * KC;
#pragma unroll
        for (int i = 0; i < 4; i++) {
            int idx = tid + 256 * i;
            int r = idx >> 3, c = idx & 7;
            size_t off = (size_t)(row0 + r) * V + kb + (c << 2);
            if (off > XMAX) off = XMAX;   // finite garbage; matching w rows are zeroed
            cp16(&xs[slot][r][c << 2], x + off);
        }
        if (kb + wkl < V) {
            cp16(&ws[slot][wkl][wc << 2], g_wc + (size_t)(kb + wkl) * DIM + (wc << 2));
        } else {
            *(float4*)&ws[slot][wkl][wc << 2] = make_float4(0.f, 0.f, 0.f, 0.f);
        }
    };

    stage(0, 0);
    cp_commit();

#pragma unroll 1
    for (int s = 0; s < nstg; s++) {
        int slot = s & 1;
        if (s + 1 < nstg) {
            stage(s + 1, slot ^ 1);
            cp_commit();
            cp_wait<1>();
        } else {
            cp_commit();
            cp_wait<0>();
        }
        __syncthreads();

        const uint32_t* xsb = (const uint32_t*)&xs[slot][wr0 + l4][lm4];
        const uint32_t* wsb = (const uint32_t*)&ws[slot][lm4][l4];
#pragma unroll
        for (int kk = 0; kk < 4; kk++) {
            uint32_t a0 = xsb[kk * 8];
            uint32_t a1 = xsb[288 + kk * 8];
            uint32_t a2 = xsb[kk * 8 + 4];
            uint32_t a3 = xsb[288 + kk * 8 + 4];
#pragma unroll
            for (int j = 0; j < 4; j++) {
                uint32_t b0 = wsb[kk * 320 + j * 8];
                uint32_t b1 = wsb[kk * 320 + 160 + j * 8];
                mma8(acc[j][0], acc[j][1], acc[j][2], acc[j][3],
                     a0, a1, a2, a3, b0, b1);
            }
        }
        __syncthreads();
    }

    float* p = g_part + (size_t)split * (BATCH * DIM)
             + (size_t)(row0 + wr0 + l4) * DIM + lm4 * 2;
#pragma unroll
    for (int j = 0; j < 4; j++) {
        *(float2*)(p + j * 8)            = make_float2(acc[j][0], acc[j][1]);
        *(float2*)(p + 8 * DIM + j * 8)  = make_float2(acc[j][2], acc[j][3]);
    }
}

// ---------- kernel 2: reduce partials + bias + sigmoid (exact) ----------
__global__ void k_hidden(const float* __restrict__ b) {
    int i = blockIdx.x * 256 + threadIdx.x; // 131072 total
    float s = 0.0f;
#pragma unroll
    for (int c = 0; c < SPLITS; c++) s += g_part[(size_t)c * (BATCH * DIM) + i];
    s += b[i & 31];
    g_hs[i] = sig_exact(s);
}

// ---------- kernel 3: decoder y = sigmoid(hs @ w^T) via mma tf32 ----------
// CTA: 128 rows x NW cols. A (hs) frags cvt'd once per warp (exact rna);
// B frags raw from pre-rounded g_wc -> no in-loop cvt.
__global__ __launch_bounds__(256, 3) void k_decoder(float* __restrict__ out) {
    __shared__ __align__(16) float hs_s[128][36];   // 18432 B
    __shared__ __align__(16) float wv_s[NW][36];    // 27648 B

    int tid  = threadIdx.x;
    int warp = tid >> 5, lane = tid & 31;
    int l4 = lane >> 2, lm4 = lane & 3;
    int wr0 = warp * 16;
    int m0 = blockIdx.y * 128;
    int n0 = blockIdx.x * NW;

#pragma unroll
    for (int i = 0; i < 4; i++) {
        int idx = tid + 256 * i;
        int r = idx >> 3, c = idx & 7;
        cp16(&hs_s[r][c << 2], g_hs + (size_t)(m0 + r) * DIM + (c << 2));
    }
#pragma unroll
    for (int i = 0; i < 6; i++) {
        int idx = tid + 256 * i;
        int vrow = idx >> 3, c = idx & 7;
        int vs = n0 + vrow;
        if (vs > V - 1) vs = V - 1;
        cp16(&wv_s[vrow][c << 2], g_wc + (size_t)vs * DIM + (c << 2));
    }
    cp_commit();
    cp_wait<0>();
    __syncthreads();

    uint32_t ua[4][4];
    const float* hb = &hs_s[wr0 + l4][lm4];
#pragma unroll
    for (int kk = 0; kk < 4; kk++) {
        ua[kk][0] = tf32(hb[kk * 8]);
        ua[kk][1] = tf32(hb[288 + kk * 8]);
        ua[kk][2] = tf32(hb[kk * 8 + 4]);
        ua[kk][3] = tf32(hb[288 + kk * 8 + 4]);
    }

    int jmax = min(NW / 8, (V - n0) >> 3);   // V is a multiple of 8
    const uint32_t* wb = (const uint32_t*)&wv_s[l4][lm4];
    float* o0 = out + (size_t)(m0 + wr0 + l4) * V + n0 + lm4 * 2;
    float* o1 = o0 + (size_t)8 * V;

#pragma unroll 2
    for (int j = 0; j < jmax; j++) {
        float d0 = 0.f, d1 = 0.f, d2 = 0.f, d3 = 0.f;
#pragma unroll
        for (int kk = 0; kk < 4; kk++) {
            uint32_t b0 = wb[j * 288 + kk * 8];
            uint32_t b1 = wb[j * 288 + kk * 8 + 4];
            mma8(d0, d1, d2, d3,
                 ua[kk][0], ua[kk][1], ua[kk][2], ua[kk][3], b0, b1);
        }
        *(float2*)(o0 + j * 8) = make_float2(sig_tanh(d0), sig_tanh(d1));
        *(float2*)(o1 + j * 8) = make_float2(sig_tanh(d2), sig_tanh(d3));
    }
}

extern "C" void kernel_launch(void* const* d_in, const int* in_sizes, int n_in,
                              void* d_out, int out_size) {
    const float* x = (const float*)d_in[0];
    const float* w = (const float*)d_in[1];
    const float* b = (const float*)d_in[2];
    float* out = (float*)d_out;

    k_wconv<<<(V * DIM + 1023) / 1024, 256>>>(w);
    k_encoder<<<dim3(BATCH / 128, SPLITS), 256>>>(x);
    k_hidden<<<(BATCH * DIM) / 256, 256>>>(b);
    k_decoder<<<dim3((V + NW - 1) / NW, BATCH / 128), 256>>>(out);
}